// round 6
// baseline (speedup 1.0000x reference)
#include <cuda_runtime.h>

// Problem constants (fixed by the dataset: node_idx=28, P=320, D=3, sigma=10)
#define NNODE 28
#define PPT   320
#define NPTS  (NNODE * PPT)   // 8960 points per tensor
#define MID   13              // (node_idx-2)/2
#define SIGMA 10.0f

#define HALF_B   160                     // B half-tile size
#define NHB      (2 * NNODE)             // 56 half-rows
#define STATS_THREADS 512
#define STATS_BLOCKS  (2 * NPTS * 4 / STATS_THREADS)   // 140 (4 threads/point)

typedef unsigned long long u64;

// Scratch (no allocations allowed -> device globals)
// g_M[dir][hb * NPTS + pt], hb = 2*node + half : g = aw + min(b.w - a.b)
__device__ float g_M[2][NHB * NPTS];       // 4 MB
__device__ float g_part[STATS_BLOCKS];
__device__ int   g_cnt;

// ---------------------------------------------------------------------------
// Packed f32x2 helpers (Blackwell sm_100+). No packed min exists; mov.b64
// unpack maps to register-pair halves and is elided by ptxas.
// ---------------------------------------------------------------------------
__device__ __forceinline__ u64 pack2(float lo, float hi) {
    u64 r;
    asm("mov.b64 %0, {%1, %2};" : "=l"(r) : "f"(lo), "f"(hi));
    return r;
}
__device__ __forceinline__ u64 fma2(u64 a, u64 b, u64 c) {
    u64 d;
    asm("fma.rn.f32x2 %0, %1, %2, %3;" : "=l"(d) : "l"(a), "l"(b), "l"(c));
    return d;
}
__device__ __forceinline__ void unpack2(u64 v, float& lo, float& hi) {
    asm("mov.b64 {%0, %1}, %2;" : "=f"(lo), "=f"(hi) : "l"(v));
}
__device__ __forceinline__ float clipf(float v) {
    return fminf(fmaxf(v, -SIGMA), SIGMA);
}

// ---------------------------------------------------------------------------
// Kernel 1: per-point per-B-half min of g = a.w + (b.w - a.b)  (clip fused).
// Grid (14, 56, 2), 160 threads. blockIdx.x: 2 A nodes (4 A pts/thread),
// blockIdx.y: B half-tile (node = y>>1, half = y&1, 160 pts in smem),
// blockIdx.z: direction. d = 2*g; the constant a.w shift commutes with all
// the min/second-min algebra in stats. Resets g_cnt for the fused final sum.
// SMEM: sXY[q] = { pack(x2q,x2q+1), pack(y2q,y2q+1) }, sZW likewise z/w.
// ---------------------------------------------------------------------------
__global__ __launch_bounds__(160, 8) void pair_min_kernel(const float* __restrict__ X,
                                                          const float* __restrict__ T) {
    if (blockIdx.x == 0 && blockIdx.y == 0 && blockIdx.z == 0 && threadIdx.x == 0)
        g_cnt = 0;

    const int dir = blockIdx.z;
    const float* __restrict__ Araw = dir ? T : X;
    const float* __restrict__ Braw = dir ? X : T;

    __shared__ ulonglong2 sXY[HALF_B / 2];
    __shared__ ulonglong2 sZW[HALF_B / 2];

    const int t = threadIdx.x;

    // Fill + clip B half-tile (one point per thread)
    {
        const int node = blockIdx.y >> 1, half = blockIdx.y & 1;
        const float* bsrc = Braw + ((size_t)node * PPT + half * HALF_B) * 3;
        float x = clipf(bsrc[3 * t + 0]);
        float y = clipf(bsrc[3 * t + 1]);
        float z = clipf(bsrc[3 * t + 2]);
        float w = fmaf(0.5f * x, x, fmaf(0.5f * y, y, 0.5f * z * z));
        float* fXY = reinterpret_cast<float*>(sXY);
        float* fZW = reinterpret_cast<float*>(sZW);
        int q = t >> 1, r = t & 1;
        fXY[q * 4 + 0 + r] = x;
        fXY[q * 4 + 2 + r] = y;
        fZW[q * 4 + 0 + r] = z;
        fZW[q * 4 + 2 + r] = w;
    }
    __syncthreads();

    // Load + clip 4 A points (2 nodes: base point = blockIdx.x*640)
    const int aBase = blockIdx.x * (2 * PPT);
    const float* asrc = Araw + (size_t)aBase * 3;
    u64 nax[4], nay[4], naz[4];
    float aw[4];
#pragma unroll
    for (int k = 0; k < 4; k++) {
        int j = t + k * 160;
        float x = clipf(asrc[3 * j + 0]);
        float y = clipf(asrc[3 * j + 1]);
        float z = clipf(asrc[3 * j + 2]);
        aw[k] = fmaf(0.5f * x, x, fmaf(0.5f * y, y, 0.5f * z * z));
        nax[k] = pack2(-x, -x);
        nay[k] = pack2(-y, -y);
        naz[k] = pack2(-z, -z);
    }

    float m[4];
#pragma unroll
    for (int k = 0; k < 4; k++) m[k] = 3.0e38f;

#pragma unroll 4
    for (int q = 0; q < HALF_B / 2; q++) {
        ulonglong2 bxy = sXY[q];   // .x = packed x pair, .y = packed y pair
        ulonglong2 bzw = sZW[q];   // .x = packed z pair, .y = packed w pair
#pragma unroll
        for (int k = 0; k < 4; k++) {
            u64 f = fma2(naz[k], bzw.x, bzw.y);
            f = fma2(nay[k], bxy.y, f);
            f = fma2(nax[k], bxy.x, f);
            float lo, hi;
            unpack2(f, lo, hi);              // register-pair alias: no SASS cost
            m[k] = fminf(m[k], fminf(lo, hi));
        }
    }

    // Epilogue: coalesced store of aw-shifted mins
    float* __restrict__ Mrow = g_M[dir] + (size_t)blockIdx.y * NPTS + aBase;
#pragma unroll
    for (int k = 0; k < 4; k++) Mrow[t + k * 160] = m[k] + aw[k];
}

// ---------------------------------------------------------------------------
// Kernel 2: per-point closed-form contribution, 4 THREADS PER POINT.
// Warp layout: 8 points per warp; lane&7 = point slot, lane>>3 = chunk (7
// nodes each). Per chunk: (m, s, a, h) over its nodes; shfl.xor(8),(16)
// butterfly merges (second-min of union = min(max(m1,m2), min(s1,s2));
// strict < keeps lower-chunk argmin on ties, valid on chunk-0 lanes).
// After the butterfly every lane holds the full result -> sum contrib/4
// over all 32 lanes (exact: x/4 pairs collapse to x in the tree).
//
//   cf = 26*m + (a<=25 ? s-m : 0) + [u<=25]*(v(e)-v(u)) + h ;  contrib = 2*cf
// Final sum fused via last-block-done (fixed-order, deterministic).
// ---------------------------------------------------------------------------
__global__ __launch_bounds__(STATS_THREADS) void stats_kernel(float* __restrict__ out) {
    const int lane = threadIdx.x & 31;
    const int warp = threadIdx.x >> 5;
    const int warp_gid = blockIdx.x * (STATS_THREADS / 32) + warp;
    const int gp = warp_gid * 8 + (lane & 7);            // 0 .. 17919
    const int chunk = lane >> 3;                         // 0..3

    const int dir = (gp >= NPTS) ? 1 : 0;
    const int p = gp - dir * NPTS;
    const int u = p / PPT;                               // node of this point
    const float* __restrict__ Md = g_M[dir] + p;

    const int h0 = (u < MID) ? 0 : MID;
    const int h1 = (u < MID) ? MID : NNODE;

    float m = 3.0e38f, s = 3.0e38f, h = 3.0e38f;
    int a = -1;
#pragma unroll
    for (int jj = 0; jj < 7; jj++) {
        int j = chunk * 7 + jj;
        float f0 = Md[(size_t)(2 * j + 0) * NPTS];
        float f1 = Md[(size_t)(2 * j + 1) * NPTS];
        float vj = fminf(f0, f1);
        if (vj < m) { s = m; m = vj; a = j; }
        else        { s = fminf(s, vj); }
        if (j >= h0 && j < h1) h = fminf(h, vj);
    }

    // Butterfly merge across the 4 chunks
#pragma unroll
    for (int off = 8; off <= 16; off <<= 1) {
        float m_o = __shfl_xor_sync(0xffffffffu, m, off);
        float s_o = __shfl_xor_sync(0xffffffffu, s, off);
        int   a_o = __shfl_xor_sync(0xffffffffu, a, off);
        float h_o = __shfl_xor_sync(0xffffffffu, h, off);
        h = fminf(h, h_o);
        float news = fminf(fmaxf(m, m_o), fminf(s, s_o));
        if (m_o < m) a = a_o;
        m = fminf(m, m_o);
        s = news;
    }

    float cf = 26.0f * m + h;
    if (a <= NNODE - 3) cf += (s - m);                   // a in 0..25
    if (u <= NNODE - 3) {                                // u in 0..25
        int idx_e = (u < MID) ? (u + MID) : (u - MID);
        float v_u = (a == u)     ? s : m;
        float v_e = (a == idx_e) ? s : m;
        cf += v_e - v_u;
    }
    float contrib = 0.25f * 2.0f * cf;                   // 4 identical copies/point

    // Warp butterfly sum (exact collapse of the 4 copies, then 8 points)
#pragma unroll
    for (int off = 16; off > 0; off >>= 1)
        contrib += __shfl_xor_sync(0xffffffffu, contrib, off);

    __shared__ float wsum[STATS_THREADS / 32];
    if (lane == 0) wsum[warp] = contrib;
    __syncthreads();

    if (warp == 0) {
        float v = (lane < STATS_THREADS / 32) ? wsum[lane] : 0.0f;
#pragma unroll
        for (int off = 8; off > 0; off >>= 1)
            v += __shfl_xor_sync(0xffffffffu, v, off);
        if (lane == 0) {
            g_part[blockIdx.x] = v;
            __threadfence();
            int old = atomicAdd(&g_cnt, 1);
            if (old == STATS_BLOCKS - 1) {               // last block: all parts visible
                float ssum = 0.0f;
                for (int i = 0; i < STATS_BLOCKS; i++) ssum += g_part[i];
                out[0] = ssum;
            }
        }
    }
}

extern "C" void kernel_launch(void* const* d_in, const int* in_sizes, int n_in,
                              void* d_out, int out_size) {
    const float* X = (const float*)d_in[0];       // X_v        [28,320,3] f32
    const float* T = (const float*)d_in[1];       // target_X_v [28,320,3] f32
    (void)in_sizes; (void)n_in; (void)out_size;   // node_idx fixed at 28

    dim3 g1(NNODE / 2, NHB, 2);                   // (14, 56, 2)
    pair_min_kernel<<<g1, 160>>>(X, T);

    stats_kernel<<<STATS_BLOCKS, STATS_THREADS>>>((float*)d_out);
}